// round 2
// baseline (speedup 1.0000x reference)
#include <cuda_runtime.h>
#include <math.h>

#define NN 100000
#define EE 800000
#define H  32
#define NL 4

// ---------------- scratch (device globals: no allocation allowed) ----------------
__device__ float g_h[NN*H];
__device__ float g_e[EE*H];
__device__ float g_enew[EE*H];
__device__ float g_Ah[NN*H];
__device__ float g_Bh[NN*H];
__device__ float g_Uh[NN*H];
__device__ float g_Vh[NN*H];
__device__ float g_hnew[NN*H];
__device__ float g_num[NN*H];
__device__ float g_den[NN*H];
// [0:32) sum_h, [32:64) sq_h, [64:96) sum_e, [96:128) sq_e
__device__ float g_stats[128];

#define FULL 0xffffffffu

// ---------------- input projection: out[i][j] = x[i]*w[j] + b[j] ----------------
__global__ void proj_kernel(const float* __restrict__ x, const float* __restrict__ w,
                            const float* __restrict__ b, float* __restrict__ out, int n)
{
    int total = n * H;
    for (int t = blockIdx.x * blockDim.x + threadIdx.x; t < total;
         t += gridDim.x * blockDim.x) {
        int row = t >> 5, lane = t & 31;
        out[t] = x[row] * w[lane] + b[lane];
    }
}

// ---------------- 4 fused node GEMMs: Ah,Bh,Uh,Vh = h @ {A,B,U,V} + bias ----------
__global__ void node_gemm4(const float* __restrict__ h,
                           const float* __restrict__ Aw, const float* __restrict__ Ab,
                           const float* __restrict__ Bw, const float* __restrict__ Bb,
                           const float* __restrict__ Uw, const float* __restrict__ Ub,
                           const float* __restrict__ Vw, const float* __restrict__ Vb,
                           int n)
{
    __shared__ float wA[H*H], wB[H*H], wU[H*H], wV[H*H];
    __shared__ float bA[H], bB[H], bU[H], bV[H];
    for (int i = threadIdx.x; i < H*H; i += blockDim.x) {
        wA[i] = Aw[i]; wB[i] = Bw[i]; wU[i] = Uw[i]; wV[i] = Vw[i];
    }
    if (threadIdx.x < H) {
        bA[threadIdx.x] = Ab[threadIdx.x];
        bB[threadIdx.x] = Bb[threadIdx.x];
        bU[threadIdx.x] = Ub[threadIdx.x];
        bV[threadIdx.x] = Vb[threadIdx.x];
    }
    __syncthreads();

    int lane = threadIdx.x & 31;
    int warp = threadIdx.x >> 5;
    int wpb  = blockDim.x >> 5;
    int stride = gridDim.x * wpb;
    for (int row = blockIdx.x * wpb + warp; row < n; row += stride) {
        float hv = h[row*H + lane];
        float a = bA[lane], b = bB[lane], u = bU[lane], v = bV[lane];
        #pragma unroll
        for (int k = 0; k < H; k++) {
            float hk = __shfl_sync(FULL, hv, k);
            a += hk * wA[k*H + lane];
            b += hk * wB[k*H + lane];
            u += hk * wU[k*H + lane];
            v += hk * wV[k*H + lane];
        }
        g_Ah[row*H + lane] = a;
        g_Bh[row*H + lane] = b;
        g_Uh[row*H + lane] = u;
        g_Vh[row*H + lane] = v;
    }
}

// ------ edge kernel: Ce GEMM + gather + e_new + sigma scatter + e_new stats ------
__global__ void edge_kernel(const float* __restrict__ e,
                            const float* __restrict__ Cw, const float* __restrict__ Cb,
                            const int* __restrict__ src, const int* __restrict__ dst,
                            int ne)
{
    __shared__ float wC[H*H];
    __shared__ float bC[H];
    __shared__ float ssum[H], ssq[H];
    for (int i = threadIdx.x; i < H*H; i += blockDim.x) wC[i] = Cw[i];
    if (threadIdx.x < H) {
        bC[threadIdx.x] = Cb[threadIdx.x];
        ssum[threadIdx.x] = 0.f;
        ssq[threadIdx.x] = 0.f;
    }
    __syncthreads();

    int lane = threadIdx.x & 31;
    int warp = threadIdx.x >> 5;
    int wpb  = blockDim.x >> 5;
    int stride = gridDim.x * wpb;
    float ls = 0.f, lq = 0.f;
    for (int eid = blockIdx.x * wpb + warp; eid < ne; eid += stride) {
        int s = src[eid], d = dst[eid];
        float ev = e[eid*H + lane];
        float ce = bC[lane];
        #pragma unroll
        for (int k = 0; k < H; k++) {
            float ek = __shfl_sync(FULL, ev, k);
            ce += ek * wC[k*H + lane];
        }
        float enew = g_Ah[d*H + lane] + g_Bh[s*H + lane] + ce;
        g_enew[eid*H + lane] = enew;
        ls += enew; lq += enew * enew;
        float sig = 1.0f / (1.0f + expf(-enew));
        atomicAdd(&g_num[d*H + lane], sig * g_Vh[s*H + lane]);
        atomicAdd(&g_den[d*H + lane], sig);
    }
    atomicAdd(&ssum[lane], ls);
    atomicAdd(&ssq[lane], lq);
    __syncthreads();
    if (threadIdx.x < H) {
        atomicAdd(&g_stats[64 + threadIdx.x], ssum[threadIdx.x]);
        atomicAdd(&g_stats[96 + threadIdx.x], ssq[threadIdx.x]);
    }
}

// ---------------- node finalize: hnew = Uh + num/(den+eps); accumulate stats -----
__global__ void node_fin_stats(int n)
{
    __shared__ float ssum[H], ssq[H];
    if (threadIdx.x < H) { ssum[threadIdx.x] = 0.f; ssq[threadIdx.x] = 0.f; }
    __syncthreads();

    int lane = threadIdx.x & 31;
    float ls = 0.f, lq = 0.f;
    int total = n * H;
    for (int t = blockIdx.x * blockDim.x + threadIdx.x; t < total;
         t += gridDim.x * blockDim.x) {
        float v = g_Uh[t] + g_num[t] / (g_den[t] + 1e-6f);
        g_hnew[t] = v;
        ls += v; lq += v * v;
    }
    atomicAdd(&ssum[lane], ls);
    atomicAdd(&ssq[lane], lq);
    __syncthreads();
    if (threadIdx.x < H) {
        atomicAdd(&g_stats[threadIdx.x],      ssum[threadIdx.x]);
        atomicAdd(&g_stats[H + threadIdx.x],  ssq[threadIdx.x]);
    }
}

// ---------------- h += relu(BN(hnew)) --------------------------------------------
__global__ void node_update(float* __restrict__ h,
                            const float* __restrict__ gamma, const float* __restrict__ beta,
                            int n)
{
    int lane0 = threadIdx.x & 31;
    float inv_n = 1.0f / (float)n;
    float mean = g_stats[lane0] * inv_n;
    float var  = g_stats[H + lane0] * inv_n - mean * mean;
    float sc   = rsqrtf(var + 1e-5f) * gamma[lane0];
    float bt   = beta[lane0];
    int total = n * H;
    for (int t = blockIdx.x * blockDim.x + threadIdx.x; t < total;
         t += gridDim.x * blockDim.x) {
        float v = (g_hnew[t] - mean) * sc + bt;
        h[t] += fmaxf(v, 0.f);
    }
}

// ---------------- e += relu(BN(e_new)) --------------------------------------------
__global__ void edge_update(float* __restrict__ e,
                            const float* __restrict__ gamma, const float* __restrict__ beta,
                            int ne)
{
    int lane0 = threadIdx.x & 31;
    float inv_n = 1.0f / (float)ne;
    float mean = g_stats[64 + lane0] * inv_n;
    float var  = g_stats[96 + lane0] * inv_n - mean * mean;
    float sc   = rsqrtf(var + 1e-5f) * gamma[lane0];
    float bt   = beta[lane0];
    int total = ne * H;
    for (int t = blockIdx.x * blockDim.x + threadIdx.x; t < total;
         t += gridDim.x * blockDim.x) {
        float v = (g_enew[t] - mean) * sc + bt;
        e[t] += fmaxf(v, 0.f);
    }
}

// ---------------- score predictor: relu(concat @ W1 + b1) @ W2 + b2 --------------
__global__ void score_kernel(const float* __restrict__ h, const float* __restrict__ e,
                             const int* __restrict__ src, const int* __restrict__ dst,
                             const float* __restrict__ W1, const float* __restrict__ b1,
                             const float* __restrict__ W2, const float* __restrict__ b2,
                             float* __restrict__ out, int ne)
{
    __shared__ float w1[96*H];
    __shared__ float sb1[H], sw2[H];
    __shared__ float sb2;
    for (int i = threadIdx.x; i < 96*H; i += blockDim.x) w1[i] = W1[i];
    if (threadIdx.x < H) { sb1[threadIdx.x] = b1[threadIdx.x]; sw2[threadIdx.x] = W2[threadIdx.x]; }
    if (threadIdx.x == 0) sb2 = b2[0];
    __syncthreads();

    int lane = threadIdx.x & 31;
    int warp = threadIdx.x >> 5;
    int wpb  = blockDim.x >> 5;
    int stride = gridDim.x * wpb;
    for (int eid = blockIdx.x * wpb + warp; eid < ne; eid += stride) {
        int s = src[eid], d = dst[eid];
        float zs = h[s*H + lane];
        float zd = h[d*H + lane];
        float ze = e[eid*H + lane];
        float hid = sb1[lane];
        #pragma unroll
        for (int k = 0; k < H; k++) {
            hid += __shfl_sync(FULL, zs, k) * w1[k*H + lane];
            hid += __shfl_sync(FULL, zd, k) * w1[(H + k)*H + lane];
            hid += __shfl_sync(FULL, ze, k) * w1[(2*H + k)*H + lane];
        }
        hid = fmaxf(hid, 0.f);
        float p = hid * sw2[lane];
        #pragma unroll
        for (int off = 16; off > 0; off >>= 1)
            p += __shfl_xor_sync(FULL, p, off);
        if (lane == 0) out[eid] = p + sb2;
    }
}

// ==================================================================================
extern "C" void kernel_launch(void* const* d_in, const int* in_sizes, int n_in,
                              void* d_out, int out_size)
{
    const float* x    = (const float*)d_in[0];
    const float* ein  = (const float*)d_in[1];
    const int*   eidx = (const int*)  d_in[2];
    const float* pe_w = (const float*)d_in[3];
    const float* pe_b = (const float*)d_in[4];
    const float* ed_w = (const float*)d_in[5];
    const float* ed_b = (const float*)d_in[6];
    const float* A_w  = (const float*)d_in[7];
    const float* A_b  = (const float*)d_in[8];
    const float* B_w  = (const float*)d_in[9];
    const float* B_b  = (const float*)d_in[10];
    const float* C_w  = (const float*)d_in[11];
    const float* C_b  = (const float*)d_in[12];
    const float* U_w  = (const float*)d_in[13];
    const float* U_b  = (const float*)d_in[14];
    const float* V_w  = (const float*)d_in[15];
    const float* V_b  = (const float*)d_in[16];
    const float* bnhg = (const float*)d_in[17];
    const float* bnhb = (const float*)d_in[18];
    const float* bneg = (const float*)d_in[19];
    const float* bneb = (const float*)d_in[20];
    const float* W1_w = (const float*)d_in[21];
    const float* W1_b = (const float*)d_in[22];
    const float* W2_w = (const float*)d_in[23];
    const float* W2_b = (const float*)d_in[24];
    float* out = (float*)d_out;

    const int n  = in_sizes[0];   // N (x is [N,1])
    const int ne = in_sizes[1];   // E (e is [E,1])
    const int* src = eidx;
    const int* dst = eidx + ne;

    // CRITICAL: all device-symbol pointers passed to kernels must come from
    // cudaGetSymbolAddress — passing the symbol directly from host code hands
    // the kernel the HOST shadow address (silently dereferenceable on GB300
    // via ATS), splitting state across two memory spaces.
    void *p_num, *p_den, *p_stats, *p_h, *p_e;
    cudaGetSymbolAddress(&p_num,   g_num);
    cudaGetSymbolAddress(&p_den,   g_den);
    cudaGetSymbolAddress(&p_stats, g_stats);
    cudaGetSymbolAddress(&p_h,     g_h);
    cudaGetSymbolAddress(&p_e,     g_e);
    float* h_ptr = (float*)p_h;
    float* e_ptr = (float*)p_e;

    const int TB = 256;
    const int G_NODE = 1024;
    const int G_EDGE = 4096;

    // input projections
    proj_kernel<<<G_NODE, TB>>>(x,   pe_w, pe_b, h_ptr, n);
    proj_kernel<<<G_EDGE, TB>>>(ein, ed_w, ed_b, e_ptr, ne);

    for (int l = 0; l < NL; l++) {
        cudaMemsetAsync(p_num,   0, (size_t)n * H * sizeof(float));
        cudaMemsetAsync(p_den,   0, (size_t)n * H * sizeof(float));
        cudaMemsetAsync(p_stats, 0, 128 * sizeof(float));

        node_gemm4<<<G_NODE, TB>>>(h_ptr,
                                   A_w + l*H*H, A_b + l*H,
                                   B_w + l*H*H, B_b + l*H,
                                   U_w + l*H*H, U_b + l*H,
                                   V_w + l*H*H, V_b + l*H, n);

        edge_kernel<<<G_EDGE, TB>>>(e_ptr, C_w + l*H*H, C_b + l*H, src, dst, ne);

        node_fin_stats<<<G_NODE, TB>>>(n);

        node_update<<<G_NODE, TB>>>(h_ptr, bnhg + l*H, bnhb + l*H, n);
        edge_update<<<G_EDGE, TB>>>(e_ptr, bneg + l*H, bneb + l*H, ne);
    }

    score_kernel<<<G_EDGE, TB>>>(h_ptr, e_ptr, src, dst,
                                 W1_w, W1_b, W2_w, W2_b, out, ne);
}